// round 2
// baseline (speedup 1.0000x reference)
#include <cuda_runtime.h>
#include <math.h>

#define BS 512
#define NN 128
#define HEADS 8
#define DIN 64
#define DOUT 64

// One block per (batch, head). 256 threads.
// smem: s_mem[0:4096)   = h chunk [128 rows][32 k]   (phase 1/2), later h_prime lower half
//       s_mem[4096:8192)= w [64 k][64 o]             (phase 1/2), later h_prime upper half
// After GEMM, s_mem becomes h_prime[128][64] (stride 64).
__global__ __launch_bounds__(256)
void gat_fused(const float* __restrict__ h,
               const int* __restrict__ adj,        // bool shipped as int32 by harness
               const float* __restrict__ w,
               const float* __restrict__ a_src,
               const float* __restrict__ a_dst,
               const float* __restrict__ bias,
               float* __restrict__ out)
{
    __shared__ float s_mem[8192];             // 32 KB
    __shared__ float s_src[NN], s_dst[NN];
    __shared__ float s_asrc[DOUT], s_adst[DOUT], s_bias[DOUT];

    const int bh   = blockIdx.x;
    const int b    = bh >> 3;
    const int head = bh & 7;
    const int tid  = threadIdx.x;
    const int tx   = tid & 15;      // output-col group (4 cols each)
    const int ty   = tid >> 4;      // output-row group (8 rows, stride 16)
    const int lane = tid & 31;
    const int wid  = tid >> 5;

    // ---- Phase 0: small vectors + w into smem ----
    if (tid < DOUT) {
        s_asrc[tid] = a_src[head * DOUT + tid];
        s_adst[tid] = a_dst[head * DOUT + tid];
        s_bias[tid] = bias[tid];
    }
    {
        const float* wp = w + head * DIN * DOUT;
        #pragma unroll
        for (int m = 0; m < 16; m++) {
            int idx = tid + 256 * m;
            s_mem[4096 + idx] = wp[idx];
        }
    }

    // ---- Phase 1+2: GEMM h[b] @ w[head] -> acc (8 rows x 4 cols per thread) ----
    float acc[8][4];
    #pragma unroll
    for (int r = 0; r < 8; r++)
        #pragma unroll
        for (int c = 0; c < 4; c++) acc[r][c] = 0.f;

    const float* hg = h + (size_t)b * NN * DIN;

    #pragma unroll
    for (int kb = 0; kb < 2; kb++) {
        if (kb) __syncthreads();   // previous GEMM pass done reading chunk
        // load h[:, kb*32 : kb*32+32] -> s_mem[0:4096) as [n][32]
        #pragma unroll
        for (int m = 0; m < 16; m++) {
            int idx = tid + 256 * m;
            int n = idx >> 5, kk = idx & 31;
            s_mem[idx] = hg[n * DIN + kb * 32 + kk];
        }
        __syncthreads();           // chunk (and, on kb=0, w + vectors) visible

        #pragma unroll
        for (int k2 = 0; k2 < 32; k2 += 4) {
            const int kg = (kb * 32 + k2) * 64 + tx * 4;
            float4 b0 = *(const float4*)&s_mem[4096 + kg];
            float4 b1 = *(const float4*)&s_mem[4096 + kg + 64];
            float4 b2 = *(const float4*)&s_mem[4096 + kg + 128];
            float4 b3 = *(const float4*)&s_mem[4096 + kg + 192];
            #pragma unroll
            for (int r = 0; r < 8; r++) {
                float4 a4 = *(const float4*)&s_mem[(ty + 16 * r) * 32 + k2];
                acc[r][0] = fmaf(a4.x, b0.x, acc[r][0]);
                acc[r][1] = fmaf(a4.x, b0.y, acc[r][1]);
                acc[r][2] = fmaf(a4.x, b0.z, acc[r][2]);
                acc[r][3] = fmaf(a4.x, b0.w, acc[r][3]);
                acc[r][0] = fmaf(a4.y, b1.x, acc[r][0]);
                acc[r][1] = fmaf(a4.y, b1.y, acc[r][1]);
                acc[r][2] = fmaf(a4.y, b1.z, acc[r][2]);
                acc[r][3] = fmaf(a4.y, b1.w, acc[r][3]);
                acc[r][0] = fmaf(a4.z, b2.x, acc[r][0]);
                acc[r][1] = fmaf(a4.z, b2.y, acc[r][1]);
                acc[r][2] = fmaf(a4.z, b2.z, acc[r][2]);
                acc[r][3] = fmaf(a4.z, b2.w, acc[r][3]);
                acc[r][0] = fmaf(a4.w, b3.x, acc[r][0]);
                acc[r][1] = fmaf(a4.w, b3.y, acc[r][1]);
                acc[r][2] = fmaf(a4.w, b3.z, acc[r][2]);
                acc[r][3] = fmaf(a4.w, b3.w, acc[r][3]);
            }
        }
    }

    // ---- Phase 3: write h_prime over s_mem; tanh-dot reductions -> s_src/s_dst ----
    __syncthreads();   // all GEMM reads of chunk/w complete before overwrite
    #pragma unroll
    for (int r = 0; r < 8; r++) {
        const int row = ty + 16 * r;
        float4 v = make_float4(acc[r][0], acc[r][1], acc[r][2], acc[r][3]);
        *(float4*)&s_mem[row * 64 + tx * 4] = v;

        float ps = 0.f, pd = 0.f;
        #pragma unroll
        for (int c = 0; c < 4; c++) {
            float t = tanhf(acc[r][c]);
            ps = fmaf(t, s_asrc[tx * 4 + c], ps);
            pd = fmaf(t, s_adst[tx * 4 + c], pd);
        }
        // reduce over tx: 16-lane halves of the warp hold the same row
        #pragma unroll
        for (int o = 8; o >= 1; o >>= 1) {
            ps += __shfl_xor_sync(0xffffffffu, ps, o);
            pd += __shfl_xor_sync(0xffffffffu, pd, o);
        }
        if (tx == 0) { s_src[row] = ps; s_dst[row] = pd; }
    }
    __syncthreads();

    // ---- Phase 4: masked softmax + sparse aggregation. One warp per row. ----
    const int* adjb = adj + (size_t)b * NN * NN;
    float* outp = out + (size_t)bh * NN * DOUT;

    for (int t = 0; t < 16; t++) {
        const int i = wid + 8 * t;
        const int* arow = adjb + i * NN;
        const float src_i = s_src[i];

        float eq[4];
        bool  act[4];
        float rmax = -1e30f;
        #pragma unroll
        for (int q = 0; q < 4; q++) {
            const int j = q * 32 + lane;
            act[q] = (arow[j] != 0);
            float e = src_i + s_dst[j];
            e = (e > 0.f) ? e : 0.2f * e;            // leaky_relu(0.2)
            eq[q] = act[q] ? e : -1e30f;
            rmax = fmaxf(rmax, eq[q]);
        }
        #pragma unroll
        for (int o = 16; o >= 1; o >>= 1)
            rmax = fmaxf(rmax, __shfl_xor_sync(0xffffffffu, rmax, o));

        float pq[4];
        float denom = 0.f;
        #pragma unroll
        for (int q = 0; q < 4; q++) {
            pq[q] = act[q] ? __expf(eq[q] - rmax) : 0.f;
            denom += pq[q];
        }
        #pragma unroll
        for (int o = 16; o >= 1; o >>= 1)
            denom += __shfl_xor_sync(0xffffffffu, denom, o);
        const float inv = (denom > 0.f) ? (1.0f / denom) : 0.f;   // NaN guard

        // sparse aggregation: only ~8 of 128 neighbors are active
        float o0 = 0.f, o1 = 0.f;
        #pragma unroll
        for (int q = 0; q < 4; q++) {
            unsigned m = __ballot_sync(0xffffffffu, pq[q] > 0.f);
            while (m) {
                const int sl = __ffs(m) - 1;
                m &= m - 1;
                const float p = __shfl_sync(0xffffffffu, pq[q], sl);
                const int j = q * 32 + sl;
                o0 = fmaf(p, s_mem[j * 64 + lane], o0);
                o1 = fmaf(p, s_mem[j * 64 + 32 + lane], o1);
            }
        }
        outp[i * 64 + lane]      = fmaf(o0, inv, s_bias[lane]);
        outp[i * 64 + 32 + lane] = fmaf(o1, inv, s_bias[32 + lane]);
    }
}

extern "C" void kernel_launch(void* const* d_in, const int* in_sizes, int n_in,
                              void* d_out, int out_size) {
    const float* h     = (const float*)d_in[0];
    const int*   adj   = (const int*)d_in[1];     // bool -> int32 per harness dtype set
    const float* w     = (const float*)d_in[2];
    const float* a_src = (const float*)d_in[3];
    const float* a_dst = (const float*)d_in[4];
    const float* bias  = (const float*)d_in[5];
    float*       out   = (float*)d_out;

    gat_fused<<<BS * HEADS, 256>>>(h, adj, w, a_src, a_dst, bias, out);
}

// round 3
// speedup vs baseline: 1.3523x; 1.3523x over previous
#include <cuda_runtime.h>
#include <math.h>

#define BS 512
#define NN 128
#define HEADS 8
#define DIN 64
#define DOUT 64

__device__ __forceinline__ float tanh_fast(float x) {
    float y;
    asm("tanh.approx.f32 %0, %1;" : "=f"(y) : "f"(x));
    return y;
}

// One block per (batch, head). 256 threads, 3 blocks/SM target.
// smem: s_mem[0:4096)   = h chunk [128 rows][32 k]   (GEMM), later h_prime lower half
//       s_mem[4096:8192)= w [64 k][64 o]             (GEMM), later h_prime upper half
__global__ __launch_bounds__(256, 3)
void gat_fused(const float* __restrict__ h,
               const int* __restrict__ adj,        // bool shipped as int32
               const float* __restrict__ w,
               const float* __restrict__ a_src,
               const float* __restrict__ a_dst,
               const float* __restrict__ bias,
               float* __restrict__ out)
{
    __shared__ float s_mem[8192];             // 32 KB
    __shared__ float s_src[NN], s_dst[NN];
    __shared__ float s_asrc[DOUT], s_adst[DOUT], s_bias[DOUT];

    const int bh   = blockIdx.x;
    const int b    = bh >> 3;
    const int head = bh & 7;
    const int tid  = threadIdx.x;
    const int tx   = tid & 15;      // output-col group (4 cols each)
    const int ty   = tid >> 4;      // output-row group (8 rows, stride 16)
    const int lane = tid & 31;
    const int wid  = tid >> 5;

    // ---- Phase 0: small vectors + w into smem (vectorized) ----
    if (tid < DOUT) {
        s_asrc[tid] = a_src[head * DOUT + tid];
        s_adst[tid] = a_dst[head * DOUT + tid];
        s_bias[tid] = bias[tid];
    }
    {
        const float4* wp4 = (const float4*)(w + head * DIN * DOUT);
        float4* s4 = (float4*)(s_mem + 4096);
        #pragma unroll
        for (int m = 0; m < 4; m++) s4[tid + 256 * m] = wp4[tid + 256 * m];
    }

    // ---- GEMM h[b] @ w[head] -> acc (8 rows x 4 cols per thread) ----
    float acc[8][4];
    #pragma unroll
    for (int r = 0; r < 8; r++)
        #pragma unroll
        for (int c = 0; c < 4; c++) acc[r][c] = 0.f;

    const float* hg = h + (size_t)b * NN * DIN;

    #pragma unroll
    for (int kb = 0; kb < 2; kb++) {
        if (kb) __syncthreads();   // previous pass done reading chunk
        // load h[:, kb*32 : +32] -> s_mem[0:4096) as [n][32], float4
        {
            float4* s4 = (float4*)s_mem;
            #pragma unroll
            for (int m = 0; m < 4; m++) {
                int idx4 = tid + 256 * m;          // 1024 float4 total
                int n = idx4 >> 3, k4 = idx4 & 7;  // 8 float4 per row
                s4[idx4] = *(const float4*)&hg[n * DIN + kb * 32 + k4 * 4];
            }
        }
        __syncthreads();

        #pragma unroll
        for (int k2 = 0; k2 < 32; k2 += 4) {
            const int kg = (kb * 32 + k2) * 64 + tx * 4;
            float4 b0 = *(const float4*)&s_mem[4096 + kg];
            float4 b1 = *(const float4*)&s_mem[4096 + kg + 64];
            float4 b2 = *(const float4*)&s_mem[4096 + kg + 128];
            float4 b3 = *(const float4*)&s_mem[4096 + kg + 192];
            #pragma unroll
            for (int r = 0; r < 8; r++) {
                float4 a4 = *(const float4*)&s_mem[(ty + 16 * r) * 32 + k2];
                acc[r][0] = fmaf(a4.x, b0.x, acc[r][0]);
                acc[r][1] = fmaf(a4.x, b0.y, acc[r][1]);
                acc[r][2] = fmaf(a4.x, b0.z, acc[r][2]);
                acc[r][3] = fmaf(a4.x, b0.w, acc[r][3]);
                acc[r][0] = fmaf(a4.y, b1.x, acc[r][0]);
                acc[r][1] = fmaf(a4.y, b1.y, acc[r][1]);
                acc[r][2] = fmaf(a4.y, b1.z, acc[r][2]);
                acc[r][3] = fmaf(a4.y, b1.w, acc[r][3]);
                acc[r][0] = fmaf(a4.z, b2.x, acc[r][0]);
                acc[r][1] = fmaf(a4.z, b2.y, acc[r][1]);
                acc[r][2] = fmaf(a4.z, b2.z, acc[r][2]);
                acc[r][3] = fmaf(a4.z, b2.w, acc[r][3]);
                acc[r][0] = fmaf(a4.w, b3.x, acc[r][0]);
                acc[r][1] = fmaf(a4.w, b3.y, acc[r][1]);
                acc[r][2] = fmaf(a4.w, b3.z, acc[r][2]);
                acc[r][3] = fmaf(a4.w, b3.w, acc[r][3]);
            }
        }
    }

    // ---- Phase 3: h_prime -> smem; tanh-dot reductions -> s_src/s_dst ----
    __syncthreads();
    #pragma unroll
    for (int r = 0; r < 8; r++) {
        const int row = ty + 16 * r;
        *(float4*)&s_mem[row * 64 + tx * 4] =
            make_float4(acc[r][0], acc[r][1], acc[r][2], acc[r][3]);

        float ps = 0.f, pd = 0.f;
        #pragma unroll
        for (int c = 0; c < 4; c++) {
            float t = tanh_fast(acc[r][c]);
            ps = fmaf(t, s_asrc[tx * 4 + c], ps);
            pd = fmaf(t, s_adst[tx * 4 + c], pd);
        }
        #pragma unroll
        for (int o = 8; o >= 1; o >>= 1) {
            ps += __shfl_xor_sync(0xffffffffu, ps, o);
            pd += __shfl_xor_sync(0xffffffffu, pd, o);
        }
        if (tx == 0) { s_src[row] = ps; s_dst[row] = pd; }
    }
    __syncthreads();

    // ---- Phase 4: masked softmax (no max-shift; |e| small) + sparse agg ----
    const int* adjb = adj + (size_t)b * NN * NN;
    float* outp = out + (size_t)bh * NN * DOUT;

    for (int t = 0; t < 16; t++) {
        const int i = wid + 8 * t;
        const int* arow = adjb + i * NN;
        const float src_i = s_src[i];

        float pq[4];
        float denom = 0.f;
        #pragma unroll
        for (int q = 0; q < 4; q++) {
            const int j = q * 32 + lane;
            float e = src_i + s_dst[j];
            e = (e > 0.f) ? e : 0.2f * e;            // leaky_relu(0.2)
            pq[q] = arow[j] ? __expf(e) : 0.f;
            denom += pq[q];
        }
        #pragma unroll
        for (int o = 16; o >= 1; o >>= 1)
            denom += __shfl_xor_sync(0xffffffffu, denom, o);
        const float inv = (denom > 0.f) ? (1.0f / denom) : 0.f;

        // sparse aggregation: only ~8 of 128 neighbors active
        float o0 = 0.f, o1 = 0.f;
        #pragma unroll
        for (int q = 0; q < 4; q++) {
            unsigned m = __ballot_sync(0xffffffffu, pq[q] > 0.f);
            while (m) {
                const int sl = __ffs(m) - 1;
                m &= m - 1;
                const float p = __shfl_sync(0xffffffffu, pq[q], sl);
                const int j = q * 32 + sl;
                o0 = fmaf(p, s_mem[j * 64 + lane], o0);
                o1 = fmaf(p, s_mem[j * 64 + 32 + lane], o1);
            }
        }
        outp[i * 64 + lane]      = fmaf(o0, inv, s_bias[lane]);
        outp[i * 64 + 32 + lane] = fmaf(o1, inv, s_bias[32 + lane]);
    }
}

extern "C" void kernel_launch(void* const* d_in, const int* in_sizes, int n_in,
                              void* d_out, int out_size) {
    const float* h     = (const float*)d_in[0];
    const int*   adj   = (const int*)d_in[1];
    const float* w     = (const float*)d_in[2];
    const float* a_src = (const float*)d_in[3];
    const float* a_dst = (const float*)d_in[4];
    const float* bias  = (const float*)d_in[5];
    float*       out   = (float*)d_out;

    gat_fused<<<BS * HEADS, 256>>>(h, adj, w, a_src, a_dst, bias, out);
}